// round 6
// baseline (speedup 1.0000x reference)
#include <cuda_runtime.h>
#include <cuda_bf16.h>
#include <cstdint>
#include <math.h>

#define B_      32
#define S_      2048
#define ENC_    1024
#define DEC_    512
#define WROW    1536
#define M_TOTAL 65536

#define BM 128
#define BN 256
#define KC 64
#define NSTAGE 16
#define NTHREADS 512

// dynamic smem layout (from 1024-aligned base)
#define OFF_VS    0
#define OFF_HS    1024
#define OFF_RED   2048
#define OFF_TILES 4096
#define STAGE_BYTES 98304
#define AHI_OFF(s) (OFF_TILES + (s) * STAGE_BYTES)
#define ALO_OFF(s) (AHI_OFF(s) + 16384)
#define BHI_OFF(s) (AHI_OFF(s) + 32768)
#define BLO_OFF(s) (AHI_OFF(s) + 65536)
#define SMEM_DYN (1024 + OFF_TILES + 2 * STAGE_BYTES)   // 201728

__device__ __align__(256) __nv_bfloat16 g_we_hi[DEC_ * ENC_];
__device__ __align__(256) __nv_bfloat16 g_we_lo[DEC_ * ENC_];
__device__ float g_hproj[B_ * DEC_];
__device__ float g_partial[2 * M_TOTAL];

// ---------------- helpers ----------------
__device__ __forceinline__ uint32_t smem_u32(const void* p) {
    uint32_t a;
    asm("{ .reg .u64 t; cvta.to.shared.u64 t, %1; cvt.u32.u64 %0, t; }" : "=r"(a) : "l"(p));
    return a;
}
__device__ __forceinline__ uint32_t swz(uint32_t o) { return o ^ ((o >> 3) & 0x70); }
__device__ __forceinline__ void cp16(uint32_t dst, const void* src) {
    asm volatile("cp.async.cg.shared.global [%0], [%1], 16;"
                 :: "r"(dst), "l"(__cvta_generic_to_global(src)) : "memory");
}
__device__ __forceinline__ uint32_t pk(__nv_bfloat16 a, __nv_bfloat16 b) {
    __nv_bfloat162 p; p.x = a; p.y = b;
    return *reinterpret_cast<uint32_t*>(&p);
}

// FFMA/ALU-only tanh: no MUFU. abs err ~2e-6 on [-8,8], exact saturation beyond.
// tanh(x) = 1 - 2/(2^(2x*log2e) + 1)
__device__ __forceinline__ float tanh_ffma(float x) {
    float xc = fminf(fmaxf(x, -8.f), 8.f);
    float y  = xc * 2.88539008177793f;                 // 2*log2(e)
    float t  = y + 12582912.f;                         // 1.5*2^23 round trick
    int   k  = __float_as_int(t) - __float_as_int(12582912.f);
    float f  = y - (t - 12582912.f);                   // f in [-0.5, 0.5]
    // 2^f, degree-5 Taylor/minimax (rel err ~2e-6 at |f|=0.5)
    float p = 1.3333558146e-3f;
    p = fmaf(p, f, 9.6181291076e-3f);
    p = fmaf(p, f, 5.5504108664e-2f);
    p = fmaf(p, f, 2.4022650696e-1f);
    p = fmaf(p, f, 6.9314718056e-1f);
    p = fmaf(p, f, 1.0f);
    float E = __int_as_float(__float_as_int(p) + (k << 23));   // 2^y
    float D = E + 1.f;
    // reciprocal: bit-trick seed + 3 Newton iterations (FFMA only)
    float r = __int_as_float(0x7EF311C3 - __float_as_int(D));
    r = r * fmaf(-D, r, 2.f);
    r = r * fmaf(-D, r, 2.f);
    r = r * fmaf(-D, r, 2.f);
    return fmaf(-2.f, r, 1.f);
}

__device__ __forceinline__ void ldsm4(uint32_t* r, uint32_t addr) {
    asm volatile("ldmatrix.sync.aligned.m8n8.x4.shared.b16 {%0,%1,%2,%3}, [%4];"
                 : "=r"(r[0]), "=r"(r[1]), "=r"(r[2]), "=r"(r[3]) : "r"(addr));
}
__device__ __forceinline__ void mma16816(float* c, const uint32_t* a, uint32_t b0, uint32_t b1) {
    asm volatile("mma.sync.aligned.m16n8k16.row.col.f32.bf16.bf16.f32 "
                 "{%0,%1,%2,%3}, {%4,%5,%6,%7}, {%8,%9}, {%0,%1,%2,%3};"
                 : "+f"(c[0]), "+f"(c[1]), "+f"(c[2]), "+f"(c[3])
                 : "r"(a[0]), "r"(a[1]), "r"(a[2]), "r"(a[3]), "r"(b0), "r"(b1));
}

// ---------------- kernel 0: We -> bf16 hi/lo ----------------
__global__ void conv_we_kernel(const float* __restrict__ W) {
    const int d = blockIdx.x, t = threadIdx.x;
    float4 x = *reinterpret_cast<const float4*>(W + (size_t)d * WROW + DEC_ + t * 4);
    float e[4] = {x.x, x.y, x.z, x.w};
    __nv_bfloat16 h[4], l[4];
#pragma unroll
    for (int i = 0; i < 4; i++) {
        h[i] = __float2bfloat16(e[i]);
        l[i] = __float2bfloat16(e[i] - __bfloat162float(h[i]));
    }
    *reinterpret_cast<uint2*>(g_we_hi + d * ENC_ + t * 4) = make_uint2(pk(h[0],h[1]), pk(h[2],h[3]));
    *reinterpret_cast<uint2*>(g_we_lo + d * ENC_ + t * 4) = make_uint2(pk(l[0],l[1]), pk(l[2],l[3]));
}

// ---------------- kernel 1: hproj ----------------
__global__ void hproj_kernel(const float* __restrict__ hidden,
                             const float* __restrict__ W,
                             const float* __restrict__ bvec) {
    __shared__ float hid[DEC_];
    const int b = blockIdx.y;
    const int n = blockIdx.x * 128 + threadIdx.x;
    for (int i = threadIdx.x; i < DEC_; i += 128) hid[i] = hidden[b * DEC_ + i];
    __syncthreads();
    const float4* wr = reinterpret_cast<const float4*>(W + (size_t)n * WROW);
    float acc = bvec[n];
#pragma unroll 8
    for (int k = 0; k < DEC_ / 4; k++) {
        float4 w = wr[k];
        acc += hid[k*4]*w.x + hid[k*4+1]*w.y + hid[k*4+2]*w.z + hid[k*4+3]*w.w;
    }
    g_hproj[b * DEC_ + n] = acc;
}

// ---------------- kernel 2: HMMA GEMM + fused epilogue ----------------
__global__ __launch_bounds__(NTHREADS, 1)
void gemm_kernel(const float* __restrict__ enc, const float* __restrict__ v) {
    extern __shared__ char sraw[];
    uint32_t sb0 = smem_u32(sraw);
    uint32_t sb = (sb0 + 1023u) & ~1023u;
    char* smem = sraw + (sb - sb0);

    const int tid  = threadIdx.x;
    const int lane = tid & 31;
    const int w    = tid >> 5;          // 0..15
    const int wm   = w >> 2;            // 0..3  (M: 32 rows each)
    const int wn   = w & 3;             // 0..3  (N: 64 cols each)
    const int g8   = lane >> 3;         // ldmatrix group
    const int r8   = lane & 7;
    const int n0   = blockIdx.x * BN;
    const int m0   = blockIdx.y * BM;
    const int batch = m0 >> 11;

    float* vs = (float*)(smem + OFF_VS);
    float* hs = (float*)(smem + OFF_HS);
    if (tid < 256) {
        vs[tid] = v[n0 + tid];
        hs[tid] = g_hproj[batch * DEC_ + n0 + tid];
    }

    const int arow = tid >> 2;
    const int acol = (tid & 3) * 16;
    const float* aptr = enc + (size_t)(m0 + arow) * ENC_ + acol;

    {
        uint32_t bh = sb + BHI_OFF(0), bl = sb + BLO_OFF(0);
#pragma unroll
        for (int i = 0; i < 4; i++) {
            int id = tid + i * NTHREADS, row = id >> 3, c = id & 7;
            uint32_t so = swz(row * 128 + c * 16);
            int g = (n0 + row) * ENC_ + c * 8;
            cp16(bh + so, g_we_hi + g);
            cp16(bl + so, g_we_lo + g);
        }
        asm volatile("cp.async.commit_group;" ::: "memory");
    }
    float4 areg[4];
#pragma unroll
    for (int j = 0; j < 4; j++) areg[j] = *reinterpret_cast<const float4*>(aptr + j * 4);

    float c[2][8][4];
#pragma unroll
    for (int mt = 0; mt < 2; mt++)
#pragma unroll
        for (int nt = 0; nt < 8; nt++)
#pragma unroll
            for (int q = 0; q < 4; q++) c[mt][nt][q] = 0.f;

    const int a_row_sel = r8 + (g8 & 1) * 8;
    const int chunk16   = (g8 >> 1) * 16;

#pragma unroll 1
    for (int kt = 0; kt < NSTAGE; kt++) {
        const int b = kt & 1;
        asm volatile("cp.async.wait_group 0;" ::: "memory");

        {
            char* ah = smem + AHI_OFF(b);
            char* al = smem + ALO_OFF(b);
#pragma unroll
            for (int j = 0; j < 4; j++) {
                float e0=areg[j].x, e1=areg[j].y, e2=areg[j].z, e3=areg[j].w;
                __nv_bfloat16 h0=__float2bfloat16(e0), h1=__float2bfloat16(e1);
                __nv_bfloat16 h2=__float2bfloat16(e2), h3=__float2bfloat16(e3);
                __nv_bfloat16 l0=__float2bfloat16(e0-__bfloat162float(h0));
                __nv_bfloat16 l1=__float2bfloat16(e1-__bfloat162float(h1));
                __nv_bfloat16 l2=__float2bfloat16(e2-__bfloat162float(h2));
                __nv_bfloat16 l3=__float2bfloat16(e3-__bfloat162float(h3));
                uint32_t off = swz(arow * 128 + (acol + j * 4) * 2);
                *reinterpret_cast<uint2*>(ah + off) = make_uint2(pk(h0,h1), pk(h2,h3));
                *reinterpret_cast<uint2*>(al + off) = make_uint2(pk(l0,l1), pk(l2,l3));
            }
        }
        __syncthreads();

        if (kt + 1 < NSTAGE) {
            const int nb = (kt + 1) & 1;
            const int kb = (kt + 1) * KC;
            uint32_t bh = sb + BHI_OFF(nb), bl = sb + BLO_OFF(nb);
#pragma unroll
            for (int i = 0; i < 4; i++) {
                int id = tid + i * NTHREADS, row = id >> 3, cc = id & 7;
                uint32_t so = swz(row * 128 + cc * 16);
                int g = (n0 + row) * ENC_ + kb + cc * 8;
                cp16(bh + so, g_we_hi + g);
                cp16(bl + so, g_we_lo + g);
            }
            asm volatile("cp.async.commit_group;" ::: "memory");
#pragma unroll
            for (int j = 0; j < 4; j++)
                areg[j] = *reinterpret_cast<const float4*>(aptr + kb + j * 4);
        }

        const uint32_t ahb = sb + AHI_OFF(b), alb = sb + ALO_OFF(b);
        const uint32_t bhb = sb + BHI_OFF(b), blb = sb + BLO_OFF(b);
#pragma unroll
        for (int k16 = 0; k16 < 4; k16++) {
            const uint32_t kby = k16 * 32 + chunk16;
            uint32_t ah[2][4], al[2][4], bh[4][4], bl[4][4];
#pragma unroll
            for (int mt = 0; mt < 2; mt++) {
                uint32_t ro = swz((wm * 32 + mt * 16 + a_row_sel) * 128 + kby);
                ldsm4(ah[mt], ahb + ro);
                ldsm4(al[mt], alb + ro);
            }
#pragma unroll
            for (int ng = 0; ng < 4; ng++) {
                uint32_t ro = swz((wn * 64 + ng * 16 + a_row_sel) * 128 + kby);
                ldsm4(bh[ng], bhb + ro);
                ldsm4(bl[ng], blb + ro);
            }
#pragma unroll
            for (int mt = 0; mt < 2; mt++)
#pragma unroll
                for (int ng = 0; ng < 4; ng++)
#pragma unroll
                    for (int s = 0; s < 2; s++) {
                        float* cc = c[mt][ng * 2 + s];
                        mma16816(cc, ah[mt], bh[ng][s], bh[ng][s + 2]);
                        mma16816(cc, ah[mt], bl[ng][s], bl[ng][s + 2]);
                        mma16816(cc, al[mt], bh[ng][s], bh[ng][s + 2]);
                    }
        }
        __syncthreads();
    }

    // ---- fused epilogue: v . tanh(C + h), FFMA-only tanh ----
    const int g = lane >> 2, q = lane & 3;
    float* red = (float*)(smem + OFF_RED);
#pragma unroll
    for (int mt = 0; mt < 2; mt++) {
        float r0 = 0.f, r1 = 0.f;
#pragma unroll
        for (int nt = 0; nt < 8; nt++) {
            int n = wn * 64 + nt * 8 + q * 2;
            float v0 = vs[n], v1 = vs[n + 1], h0 = hs[n], h1 = hs[n + 1];
            r0 += v0 * tanh_ffma(c[mt][nt][0] + h0) + v1 * tanh_ffma(c[mt][nt][1] + h1);
            r1 += v0 * tanh_ffma(c[mt][nt][2] + h0) + v1 * tanh_ffma(c[mt][nt][3] + h1);
        }
#pragma unroll
        for (int msk = 1; msk <= 2; msk <<= 1) {
            r0 += __shfl_xor_sync(0xffffffff, r0, msk);
            r1 += __shfl_xor_sync(0xffffffff, r1, msk);
        }
        if (q == 0) {
            int row = wm * 32 + mt * 16 + g;
            red[row * 4 + wn] = r0;
            red[(row + 8) * 4 + wn] = r1;
        }
    }
    __syncthreads();
    if (tid < 128)
        g_partial[(size_t)blockIdx.x * M_TOTAL + m0 + tid] =
            red[tid * 4] + red[tid * 4 + 1] + red[tid * 4 + 2] + red[tid * 4 + 3];
}

// ---------------- kernel 3: softmax ----------------
__global__ void softmax_kernel(float* __restrict__ out) {
    __shared__ float sc[S_];
    __shared__ float rb[256];
    const int b = blockIdx.x, tid = threadIdx.x;
    float lmax = -1e30f;
    for (int s = tid; s < S_; s += 256) {
        float x = g_partial[b * S_ + s] + g_partial[M_TOTAL + b * S_ + s];
        sc[s] = x;
        lmax = fmaxf(lmax, x);
    }
    rb[tid] = lmax; __syncthreads();
    for (int o = 128; o > 0; o >>= 1) {
        if (tid < o) rb[tid] = fmaxf(rb[tid], rb[tid + o]);
        __syncthreads();
    }
    const float m = rb[0]; __syncthreads();
    float ls = 0.f;
    for (int s = tid; s < S_; s += 256) {
        float e = __expf(sc[s] - m);
        sc[s] = e; ls += e;
    }
    rb[tid] = ls; __syncthreads();
    for (int o = 128; o > 0; o >>= 1) {
        if (tid < o) rb[tid] += rb[tid + o];
        __syncthreads();
    }
    const float inv = 1.f / rb[0]; __syncthreads();
    for (int s = tid; s < S_; s += 256)
        out[b * S_ + s] = sc[s] * inv;
}

// ---------------- launcher ----------------
extern "C" void kernel_launch(void* const* d_in, const int* in_sizes, int n_in,
                              void* d_out, int out_size) {
    const float* hidden = (const float*)d_in[0];
    const float* enc    = (const float*)d_in[1];
    const float* W      = (const float*)d_in[2];
    const float* bvec   = (const float*)d_in[3];
    const float* v      = (const float*)d_in[4];
    float* out          = (float*)d_out;

    cudaFuncSetAttribute(gemm_kernel, cudaFuncAttributeMaxDynamicSharedMemorySize, SMEM_DYN);

    conv_we_kernel<<<DEC_, 256>>>(W);
    hproj_kernel<<<dim3(4, B_), 128>>>(hidden, W, bvec);
    gemm_kernel<<<dim3(DEC_ / BN, M_TOTAL / BM), NTHREADS, SMEM_DYN>>>(enc, v);
    softmax_kernel<<<B_, 256>>>(out);
}

// round 7
// speedup vs baseline: 1.1735x; 1.1735x over previous
#include <cuda_runtime.h>
#include <cuda_bf16.h>
#include <cstdint>
#include <math.h>

#define B_      32
#define S_      2048
#define ENC_    1024
#define DEC_    512
#define WROW    1536
#define M_TOTAL 65536

#define BM 128
#define BN 256
#define KC 64
#define NSTAGE 16
#define NTHREADS 512

// dynamic smem layout (from 1024-aligned base)
#define OFF_VS    0
#define OFF_HS    1024
#define OFF_RED   2048
#define OFF_TILES 4096
#define STAGE_BYTES 98304        // Ahi 16K + Alo 16K + Bhi 32K + Blo 32K
#define AHI_OFF(s) (OFF_TILES + (s) * STAGE_BYTES)
#define ALO_OFF(s) (AHI_OFF(s) + 16384)
#define BHI_OFF(s) (AHI_OFF(s) + 32768)
#define BLO_OFF(s) (AHI_OFF(s) + 65536)
#define SMEM_DYN (1024 + OFF_TILES + 2 * STAGE_BYTES)   // 201728

__device__ __align__(256) __nv_bfloat16 g_we_hi[DEC_ * ENC_];
__device__ __align__(256) __nv_bfloat16 g_we_lo[DEC_ * ENC_];
__device__ __align__(256) __nv_bfloat16 g_a_hi[(size_t)M_TOTAL * ENC_];   // 128 MB
__device__ __align__(256) __nv_bfloat16 g_a_lo[(size_t)M_TOTAL * ENC_];   // 128 MB
__device__ float g_hproj[B_ * DEC_];
__device__ float g_partial[2 * M_TOTAL];

// ---------------- helpers ----------------
__device__ __forceinline__ uint32_t smem_u32(const void* p) {
    uint32_t a;
    asm("{ .reg .u64 t; cvta.to.shared.u64 t, %1; cvt.u32.u64 %0, t; }" : "=r"(a) : "l"(p));
    return a;
}
__device__ __forceinline__ uint32_t swz(uint32_t o) { return o ^ ((o >> 3) & 0x70); }
__device__ __forceinline__ void cp16(uint32_t dst, const void* src) {
    asm volatile("cp.async.cg.shared.global [%0], [%1], 16;"
                 :: "r"(dst), "l"(__cvta_generic_to_global(src)) : "memory");
}
__device__ __forceinline__ uint32_t pk(__nv_bfloat16 a, __nv_bfloat16 b) {
    __nv_bfloat162 p; p.x = a; p.y = b;
    return *reinterpret_cast<uint32_t*>(&p);
}

// FFMA/ALU-only tanh (no MUFU), abs err ~2e-6
__device__ __forceinline__ float tanh_ffma(float x) {
    float xc = fminf(fmaxf(x, -8.f), 8.f);
    float y  = xc * 2.88539008177793f;
    float t  = y + 12582912.f;
    int   k  = __float_as_int(t) - __float_as_int(12582912.f);
    float f  = y - (t - 12582912.f);
    float p = 1.3333558146e-3f;
    p = fmaf(p, f, 9.6181291076e-3f);
    p = fmaf(p, f, 5.5504108664e-2f);
    p = fmaf(p, f, 2.4022650696e-1f);
    p = fmaf(p, f, 6.9314718056e-1f);
    p = fmaf(p, f, 1.0f);
    float E = __int_as_float(__float_as_int(p) + (k << 23));
    float D = E + 1.f;
    float r = __int_as_float(0x7EF311C3 - __float_as_int(D));
    r = r * fmaf(-D, r, 2.f);
    r = r * fmaf(-D, r, 2.f);
    r = r * fmaf(-D, r, 2.f);
    return fmaf(-2.f, r, 1.f);
}

__device__ __forceinline__ void ldsm4(uint32_t* r, uint32_t addr) {
    asm volatile("ldmatrix.sync.aligned.m8n8.x4.shared.b16 {%0,%1,%2,%3}, [%4];"
                 : "=r"(r[0]), "=r"(r[1]), "=r"(r[2]), "=r"(r[3]) : "r"(addr));
}
__device__ __forceinline__ void mma16816(float* c, const uint32_t* a, uint32_t b0, uint32_t b1) {
    asm volatile("mma.sync.aligned.m16n8k16.row.col.f32.bf16.bf16.f32 "
                 "{%0,%1,%2,%3}, {%4,%5,%6,%7}, {%8,%9}, {%0,%1,%2,%3};"
                 : "+f"(c[0]), "+f"(c[1]), "+f"(c[2]), "+f"(c[3])
                 : "r"(a[0]), "r"(a[1]), "r"(a[2]), "r"(a[3]), "r"(b0), "r"(b1));
}

// ---------------- kernel 0a: We -> bf16 hi/lo ----------------
__global__ void conv_we_kernel(const float* __restrict__ W) {
    const int d = blockIdx.x, t = threadIdx.x;
    float4 x = *reinterpret_cast<const float4*>(W + (size_t)d * WROW + DEC_ + t * 4);
    float e[4] = {x.x, x.y, x.z, x.w};
    __nv_bfloat16 h[4], l[4];
#pragma unroll
    for (int i = 0; i < 4; i++) {
        h[i] = __float2bfloat16(e[i]);
        l[i] = __float2bfloat16(e[i] - __bfloat162float(h[i]));
    }
    *reinterpret_cast<uint2*>(g_we_hi + d * ENC_ + t * 4) = make_uint2(pk(h[0],h[1]), pk(h[2],h[3]));
    *reinterpret_cast<uint2*>(g_we_lo + d * ENC_ + t * 4) = make_uint2(pk(l[0],l[1]), pk(l[2],l[3]));
}

// ---------------- kernel 0b: enc -> bf16 hi/lo ----------------
__global__ void conv_a_kernel(const float* __restrict__ enc) {
    size_t i = (size_t)blockIdx.x * blockDim.x + threadIdx.x;   // float4 index
    float4 x = reinterpret_cast<const float4*>(enc)[i];
    float e[4] = {x.x, x.y, x.z, x.w};
    __nv_bfloat16 h[4], l[4];
#pragma unroll
    for (int j = 0; j < 4; j++) {
        h[j] = __float2bfloat16(e[j]);
        l[j] = __float2bfloat16(e[j] - __bfloat162float(h[j]));
    }
    reinterpret_cast<uint2*>(g_a_hi)[i] = make_uint2(pk(h[0],h[1]), pk(h[2],h[3]));
    reinterpret_cast<uint2*>(g_a_lo)[i] = make_uint2(pk(l[0],l[1]), pk(l[2],l[3]));
}

// ---------------- kernel 1: hproj ----------------
__global__ void hproj_kernel(const float* __restrict__ hidden,
                             const float* __restrict__ W,
                             const float* __restrict__ bvec) {
    __shared__ float hid[DEC_];
    const int b = blockIdx.y;
    const int n = blockIdx.x * 128 + threadIdx.x;
    for (int i = threadIdx.x; i < DEC_; i += 128) hid[i] = hidden[b * DEC_ + i];
    __syncthreads();
    const float4* wr = reinterpret_cast<const float4*>(W + (size_t)n * WROW);
    float acc = bvec[n];
#pragma unroll 8
    for (int k = 0; k < DEC_ / 4; k++) {
        float4 w = wr[k];
        acc += hid[k*4]*w.x + hid[k*4+1]*w.y + hid[k*4+2]*w.z + hid[k*4+3]*w.w;
    }
    g_hproj[b * DEC_ + n] = acc;
}

// ---------------- kernel 2: HMMA GEMM + fused epilogue ----------------
__global__ __launch_bounds__(NTHREADS, 1)
void gemm_kernel(const float* __restrict__ v) {
    extern __shared__ char sraw[];
    uint32_t sb0 = smem_u32(sraw);
    uint32_t sb = (sb0 + 1023u) & ~1023u;
    char* smem = sraw + (sb - sb0);

    const int tid  = threadIdx.x;
    const int lane = tid & 31;
    const int w    = tid >> 5;          // 0..15
    const int wm   = w >> 2;            // 0..3  (M: 32 rows)
    const int wn   = w & 3;             // 0..3  (N: 64 cols)
    const int g8   = lane >> 3;
    const int r8   = lane & 7;
    const int n0   = blockIdx.x * BN;
    const int m0   = blockIdx.y * BM;
    const int batch = m0 >> 11;

    float* vs = (float*)(smem + OFF_VS);
    float* hs = (float*)(smem + OFF_HS);
    if (tid < 256) {
        vs[tid] = v[n0 + tid];
        hs[tid] = g_hproj[batch * DEC_ + n0 + tid];
    }

    // cp.async assignments
    const int a_r = tid >> 2, a_c = tid & 3;          // A: 128 rows x 8 chunks -> 2 iters
    const int b_r = tid >> 3, b_c = tid & 7;          // B: 256 rows x 8 chunks -> 4 iters

    // prologue: stage 0
    {
        uint32_t ah = sb + AHI_OFF(0), al = sb + ALO_OFF(0);
        uint32_t bh = sb + BHI_OFF(0), bl = sb + BLO_OFF(0);
#pragma unroll
        for (int i = 0; i < 2; i++) {
            int row = a_r + i * 128 / 2 * 0 + (i ? 0 : 0);   // placeholder (replaced below)
            (void)row;
        }
#pragma unroll
        for (int i = 0; i < 2; i++) {
            int id = tid + i * NTHREADS;                     // 0..1023
            int row = id >> 3, c = id & 7;
            uint32_t so = swz(row * 128 + c * 16);
            size_t g = (size_t)(m0 + row) * ENC_ + c * 8;
            cp16(ah + so, g_a_hi + g);
            cp16(al + so, g_a_lo + g);
        }
#pragma unroll
        for (int i = 0; i < 4; i++) {
            int id = tid + i * NTHREADS;                     // 0..2047
            int row = id >> 3, c = id & 7;
            uint32_t so = swz(row * 128 + c * 16);
            size_t g = (size_t)(n0 + row) * ENC_ + c * 8;
            cp16(bh + so, g_we_hi + g);
            cp16(bl + so, g_we_lo + g);
        }
        asm volatile("cp.async.commit_group;" ::: "memory");
    }

    float c[2][8][4];
#pragma unroll
    for (int mt = 0; mt < 2; mt++)
#pragma unroll
        for (int nt = 0; nt < 8; nt++)
#pragma unroll
            for (int q = 0; q < 4; q++) c[mt][nt][q] = 0.f;

    const int a_row_sel = r8 + (g8 & 1) * 8;
    const int chunk16   = (g8 >> 1) * 16;

#pragma unroll 1
    for (int kt = 0; kt < NSTAGE; kt++) {
        const int b = kt & 1;
        asm volatile("cp.async.wait_group 0;" ::: "memory");
        __syncthreads();

        // issue loads for kt+1 into the other buffer (overlaps compute below)
        if (kt + 1 < NSTAGE) {
            const int nb = (kt + 1) & 1;
            const int kb = (kt + 1) * KC;
            uint32_t ah = sb + AHI_OFF(nb), al = sb + ALO_OFF(nb);
            uint32_t bh = sb + BHI_OFF(nb), bl = sb + BLO_OFF(nb);
#pragma unroll
            for (int i = 0; i < 2; i++) {
                int id = tid + i * NTHREADS;
                int row = id >> 3, cc = id & 7;
                uint32_t so = swz(row * 128 + cc * 16);
                size_t g = (size_t)(m0 + row) * ENC_ + kb + cc * 8;
                cp16(ah + so, g_a_hi + g);
                cp16(al + so, g_a_lo + g);
            }
#pragma unroll
            for (int i = 0; i < 4; i++) {
                int id = tid + i * NTHREADS;
                int row = id >> 3, cc = id & 7;
                uint32_t so = swz(row * 128 + cc * 16);
                size_t g = (size_t)(n0 + row) * ENC_ + kb + cc * 8;
                cp16(bh + so, g_we_hi + g);
                cp16(bl + so, g_we_lo + g);
            }
            asm volatile("cp.async.commit_group;" ::: "memory");
        }

        // compute stage kt: 4 k16 steps
        const uint32_t ahb = sb + AHI_OFF(b), alb = sb + ALO_OFF(b);
        const uint32_t bhb = sb + BHI_OFF(b), blb = sb + BLO_OFF(b);
#pragma unroll
        for (int k16 = 0; k16 < 4; k16++) {
            const uint32_t kby = k16 * 32 + chunk16;
            uint32_t ah[2][4], al[2][4];
#pragma unroll
            for (int mt = 0; mt < 2; mt++) {
                uint32_t ro = swz((wm * 32 + mt * 16 + a_row_sel) * 128 + kby);
                ldsm4(ah[mt], ahb + ro);
                ldsm4(al[mt], alb + ro);
            }
#pragma unroll
            for (int ng = 0; ng < 4; ng++) {
                uint32_t bh[4], bl[4];
                uint32_t ro = swz((wn * 64 + ng * 16 + a_row_sel) * 128 + kby);
                ldsm4(bh, bhb + ro);
                ldsm4(bl, blb + ro);
#pragma unroll
                for (int mt = 0; mt < 2; mt++)
#pragma unroll
                    for (int s = 0; s < 2; s++) {
                        float* cc = c[mt][ng * 2 + s];
                        mma16816(cc, ah[mt], bh[s], bh[s + 2]);
                        mma16816(cc, ah[mt], bl[s], bl[s + 2]);
                        mma16816(cc, al[mt], bh[s], bh[s + 2]);
                    }
            }
        }
        __syncthreads();
    }

    // ---- fused epilogue: v . tanh(C + h) ----
    const int g = lane >> 2, q = lane & 3;
    float* red = (float*)(smem + OFF_RED);
#pragma unroll
    for (int mt = 0; mt < 2; mt++) {
        float r0 = 0.f, r1 = 0.f;
#pragma unroll
        for (int nt = 0; nt < 8; nt++) {
            int n = wn * 64 + nt * 8 + q * 2;
            float v0 = vs[n], v1 = vs[n + 1], h0 = hs[n], h1 = hs[n + 1];
            r0 += v0 * tanh_ffma(c[mt][nt][0] + h0) + v1 * tanh_ffma(c[mt][nt][1] + h1);
            r1 += v0 * tanh_ffma(c[mt][nt][2] + h0) + v1 * tanh_ffma(c[mt][nt][3] + h1);
        }
#pragma unroll
        for (int msk = 1; msk <= 2; msk <<= 1) {
            r0 += __shfl_xor_sync(0xffffffff, r0, msk);
            r1 += __shfl_xor_sync(0xffffffff, r1, msk);
        }
        if (q == 0) {
            int row = wm * 32 + mt * 16 + g;
            red[row * 4 + wn] = r0;
            red[(row + 8) * 4 + wn] = r1;
        }
    }
    __syncthreads();
    if (tid < 128)
        g_partial[(size_t)blockIdx.x * M_TOTAL + m0 + tid] =
            red[tid * 4] + red[tid * 4 + 1] + red[tid * 4 + 2] + red[tid * 4 + 3];
}

// ---------------- kernel 3: softmax ----------------
__global__ void softmax_kernel(float* __restrict__ out) {
    __shared__ float sc[S_];
    __shared__ float rb[256];
    const int b = blockIdx.x, tid = threadIdx.x;
    float lmax = -1e30f;
    for (int s = tid; s < S_; s += 256) {
        float x = g_partial[b * S_ + s] + g_partial[M_TOTAL + b * S_ + s];
        sc[s] = x;
        lmax = fmaxf(lmax, x);
    }
    rb[tid] = lmax; __syncthreads();
    for (int o = 128; o > 0; o >>= 1) {
        if (tid < o) rb[tid] = fmaxf(rb[tid], rb[tid + o]);
        __syncthreads();
    }
    const float m = rb[0]; __syncthreads();
    float ls = 0.f;
    for (int s = tid; s < S_; s += 256) {
        float e = __expf(sc[s] - m);
        sc[s] = e; ls += e;
    }
    rb[tid] = ls; __syncthreads();
    for (int o = 128; o > 0; o >>= 1) {
        if (tid < o) rb[tid] += rb[tid + o];
        __syncthreads();
    }
    const float inv = 1.f / rb[0]; __syncthreads();
    for (int s = tid; s < S_; s += 256)
        out[b * S_ + s] = sc[s] * inv;
}

// ---------------- launcher ----------------
extern "C" void kernel_launch(void* const* d_in, const int* in_sizes, int n_in,
                              void* d_out, int out_size) {
    const float* hidden = (const float*)d_in[0];
    const float* enc    = (const float*)d_in[1];
    const float* W      = (const float*)d_in[2];
    const float* bvec   = (const float*)d_in[3];
    const float* v      = (const float*)d_in[4];
    float* out          = (float*)d_out;

    cudaFuncSetAttribute(gemm_kernel, cudaFuncAttributeMaxDynamicSharedMemorySize, SMEM_DYN);

    conv_we_kernel<<<DEC_, 256>>>(W);
    conv_a_kernel<<<(size_t)M_TOTAL * ENC_ / 4 / 256, 256>>>(enc);
    hproj_kernel<<<dim3(4, B_), 128>>>(hidden, W, bvec);
    gemm_kernel<<<dim3(DEC_ / BN, M_TOTAL / BM), NTHREADS, SMEM_DYN>>>(v);
    softmax_kernel<<<B_, 256>>>(out);
}